// round 11
// baseline (speedup 1.0000x reference)
#include <cuda_runtime.h>
#include <cuda_bf16.h>
#include <cstdint>

// Problem constants (E=8, R=64, B=4, S=4096, D=2048)
#define E_N   8
#define RNK   64
#define DIM   2048
#define NTOK  16384
#define TM    64
#define NTHR  256

// ---------------- device scratch ----------------
__device__ int g_count[E_N];
__device__ int g_offset[E_N];
__device__ int g_tokens[NTOK];

// ---------------- helpers ----------------
__device__ __forceinline__ uint32_t smem_u32(const void* p) {
    uint32_t a;
    asm("{ .reg .u64 t; cvta.to.shared.u64 t, %1; cvt.u32.u64 %0, t; }" : "=r"(a) : "l"(p));
    return a;
}
__device__ __forceinline__ uint32_t swz(uint32_t o) { return o ^ ((o >> 3) & 0x70); }

// split fp32 pair -> packed bf16 hi-pair + lo-pair
__device__ __forceinline__ void split2(float a, float b, uint32_t& hi, uint32_t& lo) {
    __nv_bfloat16 ha = __float2bfloat16_rn(a), hb = __float2bfloat16_rn(b);
    float ra = a - __bfloat162float(ha), rb = b - __bfloat162float(hb);
    __nv_bfloat16 la = __float2bfloat16_rn(ra), lb = __float2bfloat16_rn(rb);
    hi = ((uint32_t)__bfloat16_as_ushort(hb) << 16) | (uint32_t)__bfloat16_as_ushort(ha);
    lo = ((uint32_t)__bfloat16_as_ushort(lb) << 16) | (uint32_t)__bfloat16_as_ushort(la);
}

__device__ __forceinline__ void ldm_x4(uint32_t a, uint32_t r[4]) {
    asm volatile("ldmatrix.sync.aligned.m8n8.x4.shared.b16 {%0,%1,%2,%3}, [%4];"
                 : "=r"(r[0]), "=r"(r[1]), "=r"(r[2]), "=r"(r[3]) : "r"(a));
}
__device__ __forceinline__ void mma16816(float* c, const uint32_t* a, const uint32_t* b) {
    asm volatile("mma.sync.aligned.m16n8k16.row.col.f32.bf16.bf16.f32 "
                 "{%0,%1,%2,%3}, {%4,%5,%6,%7}, {%8,%9}, {%0,%1,%2,%3};"
                 : "+f"(c[0]), "+f"(c[1]), "+f"(c[2]), "+f"(c[3])
                 : "r"(a[0]), "r"(a[1]), "r"(a[2]), "r"(a[3]), "r"(b[0]), "r"(b[1]));
}
#define CP_COMMIT() asm volatile("cp.async.commit_group;" ::: "memory")
#define CP_WAIT0()  asm volatile("cp.async.wait_group 0;" ::: "memory")

// ---------------- SMEM layout (bytes) ----------------
// 64    : tok[64]
// 1024  : X bufs fp32 (64 rows x 288B) 18432 each; X0@1024, X1@19456 (end 37888)
//         stage2 B bufs reuse X region: {Bhi 8K, Blo 8K}=16K; B0@1024, B1@17408 (end 33792)
// 37888 : A bufs {Ahi 8K, Alo 8K}=16K; A0@37888, A1@54272 (end 70656)
//         stage2 H reuses A0 slot: Hhi@37888 (8K), Hlo@46080 (8K) (end 54272)
#define SM_TOK    64
#define SM_X0     1024
#define X_STRIDE  18432
#define X_ROWB    288
#define SM_B0     1024
#define B_STRIDE  16384
#define SM_A0     37888
#define A_STRIDE  16384
#define SM_HHI    37888
#define SM_HLO    46080
#define SMEM_BYTES 70656

// ---------------- sort kernel (single CTA) ----------------
__global__ void __launch_bounds__(1024) k_sort(const int* __restrict__ ti) {
    __shared__ int sc[E_N];
    __shared__ int sb[E_N];
    const int tid = threadIdx.x;
    const int lane = tid & 31;
    if (tid < E_N) sc[tid] = 0;
    __syncthreads();
    for (int t = tid; t < NTOK; t += 1024) {
        int e = ti[t];
        unsigned mask = __match_any_sync(0xffffffffu, e);
        int leader = __ffs(mask) - 1;
        if (lane == leader) atomicAdd(&sc[e], __popc(mask));
    }
    __syncthreads();
    if (tid == 0) {
        int acc = 0;
        for (int e = 0; e < E_N; ++e) {
            g_count[e] = sc[e];
            g_offset[e] = acc;
            sb[e] = acc;
            acc += sc[e];
        }
    }
    __syncthreads();
    for (int t = tid; t < NTOK; t += 1024) {
        int e = ti[t];
        unsigned mask = __match_any_sync(0xffffffffu, e);
        int leader = __ffs(mask) - 1;
        int prior = __popc(mask & ((1u << lane) - 1));
        int base = 0;
        if (lane == leader) base = atomicAdd(&sb[e], __popc(mask));
        base = __shfl_sync(0xffffffffu, base, leader);
        g_tokens[base + prior] = t;
    }
}

// ---------------- main kernel ----------------
__global__ void __launch_bounds__(NTHR, 2)
k_main(const float* __restrict__ x,
       const float* __restrict__ Aw,
       const float* __restrict__ Bw,
       float* __restrict__ out) {
    const int e = blockIdx.y;
    const int cnt = g_count[e];
    const int mstart = blockIdx.x * TM;
    if (mstart >= cnt) return;
    const int base = g_offset[e];

    extern __shared__ char smc[];
    const uint32_t sbu = smem_u32(smc);
    const int tid = threadIdx.x;
    const int wid = tid >> 5;
    const int lane = tid & 31;
    const int g = lane >> 2;
    const int tq = lane & 3;
    // stage-1 warp tile: m16 x n32 (4 m-groups x 2 n-groups, 8 warps)
    const int s1mg = wid >> 1;
    const int s1ng = wid & 1;
    // stage-2 warp tile: m16 x n32 (4 m-groups x 2 n-groups of the 64-chunk)
    const int s2mg = wid >> 1;
    const int s2ng = wid & 1;
    int* tok = (int*)(smc + SM_TOK);

    if (tid < TM) {
        int i = mstart + tid;
        tok[tid] = (i < cnt) ? g_tokens[base + i] : -1;
    }
    __syncthreads();

    const float* Arow = Aw + (size_t)e * RNK * DIM;
    const float* Brow = Bw + (size_t)e * DIM * RNK;

    // ldmatrix lane patterns (pre-swizzle, relative to tile row base)
    const uint32_t bpair = (uint32_t)((lane & 7) + ((lane >> 4) << 3)) * 128 +
                           (uint32_t)((lane >> 3) & 1) * 16;          // 16-row n-pair
    const uint32_t apat  = (uint32_t)(lane & 15) * 128 + (uint32_t)(lane >> 4) * 16; // m16 A-op

    // ---- X fill via cp.async: 64 rows x 64 k fp32; thread -> rows {xfr, xfr+32} ----
    const int xfr = tid >> 3, xfq = tid & 7;
    const int xt0 = tok[xfr], xt1 = tok[xfr + 32];
    const float* xp0 = x + (size_t)(xt0 < 0 ? 0 : xt0) * DIM;
    const float* xp1 = x + (size_t)(xt1 < 0 ? 0 : xt1) * DIM;
    const int xv0 = (xt0 >= 0) ? 16 : 0;
    const int xv1 = (xt1 >= 0) ? 16 : 0;

#define CPX(BUF, K0)                                                            \
    do {                                                                        \
        uint32_t d_ = sbu + SM_X0 + (BUF) * X_STRIDE + xfr * X_ROWB + xfq * 16; \
        const float* s0_ = xp0 + (K0) + xfq * 4;                                \
        const float* s1_ = xp1 + (K0) + xfq * 4;                                \
        asm volatile("cp.async.cg.shared.global [%0], [%1], 16, %2;"            \
                     :: "r"(d_), "l"(s0_), "r"(xv0));                           \
        asm volatile("cp.async.cg.shared.global [%0], [%1], 16, %2;"            \
                     :: "r"(d_ + 128), "l"(s0_ + 32), "r"(xv0));                \
        asm volatile("cp.async.cg.shared.global [%0], [%1], 16, %2;"            \
                     :: "r"(d_ + 32 * X_ROWB), "l"(s1_), "r"(xv1));             \
        asm volatile("cp.async.cg.shared.global [%0], [%1], 16, %2;"            \
                     :: "r"(d_ + 32 * X_ROWB + 128), "l"(s1_ + 32), "r"(xv1));  \
    } while (0)

    // ---- A fill: 64 r-rows x 64 k fp32; thread row fr, 4 float4 ----
    const int fr = tid >> 2, fq = tid & 3;
    float4 va[4];

#define LOAD_A(K0)                                                              \
    do {                                                                        \
        _Pragma("unroll") for (int i = 0; i < 4; ++i) va[i] =                   \
            *(const float4*)(Arow + (size_t)fr * DIM + (K0) + fq * 4 + i * 16); \
    } while (0)

#define STORE_A(BUF)                                                            \
    do {                                                                        \
        char* ah = smc + SM_A0 + (BUF) * A_STRIDE;                              \
        char* al = ah + 8192;                                                   \
        _Pragma("unroll") for (int i = 0; i < 4; ++i) {                         \
            uint32_t h0, l0, h1, l1;                                            \
            split2(va[i].x, va[i].y, h0, l0);                                   \
            split2(va[i].z, va[i].w, h1, l1);                                   \
            uint32_t off = swz((uint32_t)fr * 128 + fq * 8 + i * 32);           \
            *(uint2*)(ah + off) = make_uint2(h0, h1);                           \
            *(uint2*)(al + off) = make_uint2(l0, l1);                           \
        }                                                                       \
    } while (0)

    // ===== stage 1: H[64,64] = X[64,2048] * A_e^T, 32 k-chunks of 64 =====
    float acc1[4][4];
#pragma unroll
    for (int j = 0; j < 4; ++j)
#pragma unroll
        for (int q = 0; q < 4; ++q) acc1[j][q] = 0.f;

    CPX(0, 0);
    CP_COMMIT();
    LOAD_A(0);
    STORE_A(0);
    CP_WAIT0();
    __syncthreads();
    LOAD_A(64);

    const uint32_t xo0 = (uint32_t)(s1mg * 16 + g) * X_ROWB + tq * 8;
    const uint32_t xo1 = (uint32_t)(s1mg * 16 + 8 + g) * X_ROWB + tq * 8;

    for (int c = 0; c < 32; ++c) {
        if (c < 31) {
            CPX((c + 1) & 1, (c + 1) * 64);
            CP_COMMIT();
        }
        const char* xb = smc + SM_X0 + (c & 1) * X_STRIDE;
        const uint32_t ahB = sbu + SM_A0 + (uint32_t)(c & 1) * A_STRIDE;
#pragma unroll
        for (int kk = 0; kk < 4; ++kk) {
            float2 r0 = *(const float2*)(xb + xo0 + kk * 64);
            float2 r1 = *(const float2*)(xb + xo1 + kk * 64);
            float2 r2 = *(const float2*)(xb + xo0 + kk * 64 + 32);
            float2 r3 = *(const float2*)(xb + xo1 + kk * 64 + 32);
            uint32_t xh[4], xl[4];
            split2(r0.x, r0.y, xh[0], xl[0]);
            split2(r1.x, r1.y, xh[1], xl[1]);
            split2(r2.x, r2.y, xh[2], xl[2]);
            split2(r3.x, r3.y, xh[3], xl[3]);
#pragma unroll
            for (int jj = 0; jj < 2; ++jj) {
                uint32_t bh[4], bl[4];
                uint32_t ao = swz((uint32_t)(s1ng * 32 + jj * 16) * 128 + bpair + kk * 32);
                ldm_x4(ahB + ao, bh);
                ldm_x4(ahB + 8192 + ao, bl);
                mma16816(acc1[jj * 2], xh, bh);
                mma16816(acc1[jj * 2], xh, bl);
                mma16816(acc1[jj * 2], xl, bh);
                mma16816(acc1[jj * 2 + 1], xh, bh + 2);
                mma16816(acc1[jj * 2 + 1], xh, bl + 2);
                mma16816(acc1[jj * 2 + 1], xl, bh + 2);
            }
        }
        if (c < 31) {
            STORE_A((c + 1) & 1);
            if (c < 30) LOAD_A((c + 2) * 64);
            CP_WAIT0();
        }
        __syncthreads();
    }

    // ===== stage 2 B fill: 64 n-rows x 64 r fp32 per chunk ----
    const int bfn = tid >> 2, bfq = tid & 3;
    float4 vb[4];

#define LOAD_B(N0)                                                              \
    do {                                                                        \
        const float* src = Brow + (size_t)((N0) + bfn) * RNK + bfq * 4;         \
        _Pragma("unroll") for (int i = 0; i < 4; ++i) vb[i] =                   \
            *(const float4*)(src + i * 16);                                     \
    } while (0)

#define STORE_B(BUF)                                                            \
    do {                                                                        \
        char* bh_ = smc + SM_B0 + (BUF) * B_STRIDE;                             \
        char* bl_ = bh_ + 8192;                                                 \
        _Pragma("unroll") for (int i = 0; i < 4; ++i) {                         \
            uint32_t h0, l0, h1, l1;                                            \
            split2(vb[i].x, vb[i].y, h0, l0);                                   \
            split2(vb[i].z, vb[i].w, h1, l1);                                   \
            uint32_t off = swz((uint32_t)bfn * 128 + bfq * 8 + i * 32);         \
            *(uint2*)(bh_ + off) = make_uint2(h0, h1);                          \
            *(uint2*)(bl_ + off) = make_uint2(l0, l1);                          \
        }                                                                       \
    } while (0)

    LOAD_B(0);   // start GMEM reads early

    // ===== H -> SMEM bf16 hi/lo (fragment-consistent layout; reuses A0 slot) =====
    {
        char* hh = smc + SM_HHI;
        char* hl = smc + SM_HLO;
#pragma unroll
        for (int j = 0; j < 4; ++j) {
            int col = s1ng * 32 + j * 8 + 2 * tq;
            int r0 = s1mg * 16 + g;
            uint32_t hi, lo;
            split2(acc1[j][0], acc1[j][1], hi, lo);
            uint32_t off = swz((uint32_t)r0 * 128 + (uint32_t)col * 2);
            *(uint32_t*)(hh + off) = hi;
            *(uint32_t*)(hl + off) = lo;
            split2(acc1[j][2], acc1[j][3], hi, lo);
            uint32_t off2 = swz((uint32_t)(r0 + 8) * 128 + (uint32_t)col * 2);
            *(uint32_t*)(hh + off2) = hi;
            *(uint32_t*)(hl + off2) = lo;
        }
    }
    STORE_B(0);
    __syncthreads();

    // preload ALL H fragments into registers (reused across all 32 n-chunks)
    uint32_t hfh[4][4], hfl[4][4];
#pragma unroll
    for (int kk = 0; kk < 4; ++kk) {
        uint32_t ho = swz((uint32_t)(s2mg * 16) * 128 + apat + kk * 32);
        ldm_x4(sbu + SM_HHI + ho, hfh[kk]);
        ldm_x4(sbu + SM_HLO + ho, hfl[kk]);
    }

    // stage-2 output tokens for this warp
    const int t2a = tok[s2mg * 16 + g];
    const int t2b = tok[s2mg * 16 + 8 + g];

    LOAD_B(64);

    // ===== stage 2: O[64,2048] = H[64,64] * B_e^T, 32 n-chunks of 64 =====
    for (int nc = 0; nc < 32; ++nc) {
        float acc2[4][4];
#pragma unroll
        for (int j = 0; j < 4; ++j)
#pragma unroll
            for (int q = 0; q < 4; ++q) acc2[j][q] = 0.f;

        const uint32_t bbB = sbu + SM_B0 + (uint32_t)(nc & 1) * B_STRIDE;
#pragma unroll
        for (int kk = 0; kk < 4; ++kk) {
#pragma unroll
            for (int jj = 0; jj < 2; ++jj) {
                uint32_t bh[4], bl[4];
                uint32_t bo = swz((uint32_t)(s2ng * 32 + jj * 16) * 128 + bpair + kk * 32);
                ldm_x4(bbB + bo, bh);
                ldm_x4(bbB + 8192 + bo, bl);
                mma16816(acc2[jj * 2], hfh[kk], bh);
                mma16816(acc2[jj * 2], hfh[kk], bl);
                mma16816(acc2[jj * 2], hfl[kk], bh);
                mma16816(acc2[jj * 2 + 1], hfh[kk], bh + 2);
                mma16816(acc2[jj * 2 + 1], hfh[kk], bl + 2);
                mma16816(acc2[jj * 2 + 1], hfl[kk], bh + 2);
            }
        }

        // epilogue: direct STG.64
        const int nb0 = nc * 64 + s2ng * 32 + 2 * tq;
#pragma unroll
        for (int j = 0; j < 4; ++j) {
            int colo = nb0 + j * 8;
            if (t2a >= 0)
                *(float2*)(out + (size_t)t2a * DIM + colo) =
                    make_float2(acc2[j][0], acc2[j][1]);
            if (t2b >= 0)
                *(float2*)(out + (size_t)t2b * DIM + colo) =
                    make_float2(acc2[j][2], acc2[j][3]);
        }

        if (nc < 31) {
            STORE_B((nc + 1) & 1);
            if (nc < 30) LOAD_B((nc + 2) * 64);
        }
        __syncthreads();
    }
}

// ---------------- launch ----------------
extern "C" void kernel_launch(void* const* d_in, const int* in_sizes, int n_in,
                              void* d_out, int out_size) {
    const float* x  = (const float*)d_in[0];   // [B,S,D]
    const float* Aw = (const float*)d_in[1];   // [E,R,D]
    const float* Bw = (const float*)d_in[2];   // [E,D,R]
    const int*   ti = (const int*)d_in[3];     // [B,S]
    float* out = (float*)d_out;
    (void)in_sizes; (void)n_in; (void)out_size;

    static int smem_set = 0;
    if (!smem_set) {
        cudaFuncSetAttribute(k_main, cudaFuncAttributeMaxDynamicSharedMemorySize, SMEM_BYTES);
        smem_set = 1;
    }

    k_sort<<<1, 1024>>>(ti);
    dim3 grid(NTOK / TM, E_N, 1);
    k_main<<<grid, NTHR, SMEM_BYTES>>>(x, Aw, Bw, out);
}

// round 12
// speedup vs baseline: 1.5906x; 1.5906x over previous
#include <cuda_runtime.h>
#include <cuda_fp16.h>
#include <cstdint>

// Problem constants (E=8, R=64, B=4, S=4096, D=2048)
#define E_N   8
#define RNK   64
#define DIM   2048
#define NTOK  16384
#define TM    128
#define NTHR  512

// ---------------- device scratch ----------------
__device__ int g_count[E_N];
__device__ int g_offset[E_N];
__device__ int g_tokens[NTOK];

// ---------------- helpers ----------------
__device__ __forceinline__ uint32_t smem_u32(const void* p) {
    uint32_t a;
    asm("{ .reg .u64 t; cvta.to.shared.u64 t, %1; cvt.u32.u64 %0, t; }" : "=r"(a) : "l"(p));
    return a;
}
__device__ __forceinline__ uint32_t swz(uint32_t o) { return o ^ ((o >> 3) & 0x70); }

// pack two fp32 -> fp16x2 (a -> low half, b -> high half)
__device__ __forceinline__ uint32_t pk2(float a, float b) {
    uint32_t r;
    asm("cvt.rn.f16x2.f32 %0, %1, %2;" : "=r"(r) : "f"(b), "f"(a));
    return r;
}

__device__ __forceinline__ void ldm_x4(uint32_t a, uint32_t r[4]) {
    asm volatile("ldmatrix.sync.aligned.m8n8.x4.shared.b16 {%0,%1,%2,%3}, [%4];"
                 : "=r"(r[0]), "=r"(r[1]), "=r"(r[2]), "=r"(r[3]) : "r"(a));
}
__device__ __forceinline__ void mma16816(float* c, const uint32_t* a, const uint32_t* b) {
    asm volatile("mma.sync.aligned.m16n8k16.row.col.f32.f16.f16.f32 "
                 "{%0,%1,%2,%3}, {%4,%5,%6,%7}, {%8,%9}, {%0,%1,%2,%3};"
                 : "+f"(c[0]), "+f"(c[1]), "+f"(c[2]), "+f"(c[3])
                 : "r"(a[0]), "r"(a[1]), "r"(a[2]), "r"(a[3]), "r"(b[0]), "r"(b[1]));
}

// ---------------- SMEM layout (bytes) ----------------
// 64     : tok[128]
// 1024   : X bufs fp32 (128 rows x 288B stride) 36864 each; X0@1024, X1@37888 (end 74752)
//          stage2 B bufs reuse X region: 16K each (fp16); B0@1024, B1@17408 (end 33792)
// 74752  : A bufs fp16 8K each; A0@74752, A1@82944 (end 91136)
// 91136  : H fp16 16K (end 107520)
#define SM_TOK    64
#define SM_X0     1024
#define X_STRIDE  36864
#define X_ROWB    288
#define SM_B0     1024
#define B_STRIDE  16384
#define SM_A0     74752
#define A_STRIDE  8192
#define SM_H      91136
#define SMEM_BYTES 107520

// ---------------- sort kernel (single CTA) ----------------
__global__ void __launch_bounds__(1024) k_sort(const int* __restrict__ ti) {
    __shared__ int sc[E_N];
    __shared__ int sb[E_N];
    const int tid = threadIdx.x;
    const int lane = tid & 31;
    if (tid < E_N) sc[tid] = 0;
    __syncthreads();
    for (int t = tid; t < NTOK; t += 1024) {
        int e = ti[t];
        unsigned mask = __match_any_sync(0xffffffffu, e);
        int leader = __ffs(mask) - 1;
        if (lane == leader) atomicAdd(&sc[e], __popc(mask));
    }
    __syncthreads();
    if (tid == 0) {
        int acc = 0;
        for (int e = 0; e < E_N; ++e) {
            g_count[e] = sc[e];
            g_offset[e] = acc;
            sb[e] = acc;
            acc += sc[e];
        }
    }
    __syncthreads();
    for (int t = tid; t < NTOK; t += 1024) {
        int e = ti[t];
        unsigned mask = __match_any_sync(0xffffffffu, e);
        int leader = __ffs(mask) - 1;
        int prior = __popc(mask & ((1u << lane) - 1));
        int base = 0;
        if (lane == leader) base = atomicAdd(&sb[e], __popc(mask));
        base = __shfl_sync(0xffffffffu, base, leader);
        g_tokens[base + prior] = t;
    }
}

// ---------------- main kernel ----------------
__global__ void __launch_bounds__(NTHR, 1)
k_main(const float* __restrict__ x,
       const float* __restrict__ Aw,
       const float* __restrict__ Bw,
       float* __restrict__ out) {
    const int e = blockIdx.y;
    const int cnt = g_count[e];
    const int mstart = blockIdx.x * TM;
    if (mstart >= cnt) return;
    const int base = g_offset[e];

    extern __shared__ char smc[];
    const uint32_t sbu = smem_u32(smc);
    const int tid = threadIdx.x;
    const int wid = tid >> 5;
    const int lane = tid & 31;
    const int g = lane >> 2;
    const int tq = lane & 3;
    // stage-1 warp tile: m16 x n32
    const int s1mg = wid >> 1;   // rows s1mg*16..+16
    const int s1ng = wid & 1;    // cols s1ng*32..+32
    // stage-2 warp tile: m32 x n32
    const int s2mg = wid >> 2;   // rows s2mg*32..+32
    const int s2ng = wid & 3;    // chunk cols s2ng*32..+32
    int* tok = (int*)(smc + SM_TOK);

    if (tid < TM) {
        int i = mstart + tid;
        tok[tid] = (i < cnt) ? g_tokens[base + i] : -1;
    }
    __syncthreads();

    const float* Arow = Aw + (size_t)e * RNK * DIM;
    const float* Brow = Bw + (size_t)e * DIM * RNK;

    // ldmatrix lane patterns (pre-swizzle, relative to tile row base)
    const uint32_t bpair = (uint32_t)((lane & 7) + ((lane >> 4) << 3)) * 128 +
                           (uint32_t)((lane >> 3) & 1) * 16;          // 16-row n-pair
    const uint32_t apat  = (uint32_t)(lane & 15) * 128 + (uint32_t)(lane >> 4) * 16; // m16 A-op

    // ---- fill mappings (coalesced full 128B lines per LDG instr) ----
    const int xfr = tid >> 3, xfq = tid & 7;
    const int xt0 = tok[xfr], xt1 = tok[xfr + 64];
    const float* xp0 = x + (size_t)(xt0 < 0 ? 0 : xt0) * DIM;
    const float* xp1 = x + (size_t)(xt1 < 0 ? 0 : xt1) * DIM;
    float4 vx[4];
    const int fr = tid >> 3, fq = tid & 7;
    float4 va[2];

#define LOAD_X(K0)                                                              \
    do {                                                                        \
        float4 z = make_float4(0.f, 0.f, 0.f, 0.f);                             \
        vx[0] = (xt0 >= 0) ? *(const float4*)(xp0 + (K0) + xfq * 4) : z;        \
        vx[1] = (xt0 >= 0) ? *(const float4*)(xp0 + (K0) + 32 + xfq * 4) : z;   \
        vx[2] = (xt1 >= 0) ? *(const float4*)(xp1 + (K0) + xfq * 4) : z;        \
        vx[3] = (xt1 >= 0) ? *(const float4*)(xp1 + (K0) + 32 + xfq * 4) : z;   \
    } while (0)

#define STORE_X(BUF)                                                            \
    do {                                                                        \
        char* xb_ = smc + SM_X0 + (BUF) * X_STRIDE;                             \
        *(float4*)(xb_ + xfr * X_ROWB + xfq * 16)              = vx[0];         \
        *(float4*)(xb_ + xfr * X_ROWB + 128 + xfq * 16)        = vx[1];         \
        *(float4*)(xb_ + (xfr + 64) * X_ROWB + xfq * 16)       = vx[2];         \
        *(float4*)(xb_ + (xfr + 64) * X_ROWB + 128 + xfq * 16) = vx[3];         \
    } while (0)

#define LOAD_A(K0)                                                              \
    do {                                                                        \
        _Pragma("unroll") for (int i = 0; i < 2; ++i) va[i] =                   \
            *(const float4*)(Arow + (size_t)fr * DIM + (K0) + fq * 4 + i * 32); \
    } while (0)

#define STORE_A(BUF)                                                            \
    do {                                                                        \
        char* ah = smc + SM_A0 + (BUF) * A_STRIDE;                              \
        _Pragma("unroll") for (int i = 0; i < 2; ++i) {                         \
            uint32_t p0 = pk2(va[i].x, va[i].y);                                \
            uint32_t p1 = pk2(va[i].z, va[i].w);                                \
            uint32_t off = swz((uint32_t)fr * 128 + fq * 8 + i * 64);           \
            *(uint2*)(ah + off) = make_uint2(p0, p1);                           \
        }                                                                       \
    } while (0)

    // ===== stage 1: H[128,64] = X[128,2048] * A_e^T =====
    float acc1[4][4];
#pragma unroll
    for (int j = 0; j < 4; ++j)
#pragma unroll
        for (int q = 0; q < 4; ++q) acc1[j][q] = 0.f;

    LOAD_X(0);
    LOAD_A(0);
    STORE_X(0);
    STORE_A(0);
    __syncthreads();
    LOAD_X(64);
    LOAD_A(64);

    // fragment-read offsets within X SMEM tile
    const uint32_t xo0 = (uint32_t)(s1mg * 16 + g) * X_ROWB + tq * 8;
    const uint32_t xo1 = (uint32_t)(s1mg * 16 + 8 + g) * X_ROWB + tq * 8;

    for (int c = 0; c < 32; ++c) {
        const char* xb = smc + SM_X0 + (c & 1) * X_STRIDE;
        const uint32_t ahB = sbu + SM_A0 + (uint32_t)(c & 1) * A_STRIDE;
#pragma unroll
        for (int kk = 0; kk < 4; ++kk) {
            float2 r0 = *(const float2*)(xb + xo0 + kk * 64);
            float2 r1 = *(const float2*)(xb + xo1 + kk * 64);
            float2 r2 = *(const float2*)(xb + xo0 + kk * 64 + 32);
            float2 r3 = *(const float2*)(xb + xo1 + kk * 64 + 32);
            uint32_t xf[4];
            xf[0] = pk2(r0.x, r0.y);
            xf[1] = pk2(r1.x, r1.y);
            xf[2] = pk2(r2.x, r2.y);
            xf[3] = pk2(r3.x, r3.y);
#pragma unroll
            for (int jj = 0; jj < 2; ++jj) {
                uint32_t bh[4];
                uint32_t ao = swz((uint32_t)(s1ng * 32 + jj * 16) * 128 + bpair + kk * 32);
                ldm_x4(ahB + ao, bh);
                mma16816(acc1[jj * 2], xf, bh);
                mma16816(acc1[jj * 2 + 1], xf, bh + 2);
            }
        }
        if (c < 31) {
            STORE_X((c + 1) & 1);
            STORE_A((c + 1) & 1);
            if (c < 30) {
                LOAD_X((c + 2) * 64);
                LOAD_A((c + 2) * 64);
            }
        }
        __syncthreads();
    }

    // ===== stage 2 fills (B): 128n x 64r fp32 per chunk =====
    const int bfn = tid >> 3, bfq = tid & 7;
    float4 vb[4];

#define LOAD_B(N0)                                                              \
    do {                                                                        \
        const float* s0 = Brow + (size_t)((N0) + bfn) * RNK + bfq * 4;          \
        const float* s1 = Brow + (size_t)((N0) + bfn + 64) * RNK + bfq * 4;     \
        vb[0] = *(const float4*)(s0);                                           \
        vb[1] = *(const float4*)(s0 + 32);                                      \
        vb[2] = *(const float4*)(s1);                                           \
        vb[3] = *(const float4*)(s1 + 32);                                      \
    } while (0)

#define STORE_B(BUF)                                                            \
    do {                                                                        \
        char* bh_ = smc + SM_B0 + (BUF) * B_STRIDE;                             \
        _Pragma("unroll") for (int i = 0; i < 4; ++i) {                         \
            uint32_t p0 = pk2(vb[i].x, vb[i].y);                                \
            uint32_t p1 = pk2(vb[i].z, vb[i].w);                                \
            uint32_t row = (uint32_t)bfn + (i >> 1) * 64;                       \
            uint32_t off = swz(row * 128 + bfq * 8 + (i & 1) * 64);             \
            *(uint2*)(bh_ + off) = make_uint2(p0, p1);                          \
        }                                                                       \
    } while (0)

    LOAD_B(0);   // start GMEM reads early

    // ===== H -> SMEM fp16 (fragment-consistent layout) =====
    {
        char* hh = smc + SM_H;
#pragma unroll
        for (int j = 0; j < 4; ++j) {
            int col = s1ng * 32 + j * 8 + 2 * tq;
            int r0 = s1mg * 16 + g;
            uint32_t p0 = pk2(acc1[j][0], acc1[j][1]);
            uint32_t off = swz((uint32_t)r0 * 128 + (uint32_t)col * 2);
            *(uint32_t*)(hh + off) = p0;
            uint32_t p1 = pk2(acc1[j][2], acc1[j][3]);
            uint32_t off2 = swz((uint32_t)(r0 + 8) * 128 + (uint32_t)col * 2);
            *(uint32_t*)(hh + off2) = p1;
        }
    }
    STORE_B(0);
    __syncthreads();

    // preload ALL H fragments into registers (reused across all 16 n-chunks)
    uint32_t hf[2][4][4];
#pragma unroll
    for (int mt = 0; mt < 2; ++mt)
#pragma unroll
        for (int kk = 0; kk < 4; ++kk) {
            uint32_t ho = swz((uint32_t)(s2mg * 32 + mt * 16) * 128 + apat + kk * 32);
            ldm_x4(sbu + SM_H + ho, hf[mt][kk]);
        }

    // stage-2 output tokens for this warp
    int tko[2][2];
#pragma unroll
    for (int mt = 0; mt < 2; ++mt) {
        tko[mt][0] = tok[s2mg * 32 + mt * 16 + g];
        tko[mt][1] = tok[s2mg * 32 + mt * 16 + 8 + g];
    }

    LOAD_B(128);

    // ===== stage 2: O[128,2048] = H[128,64] * B_e^T, 16 n-chunks of 128 =====
    for (int nc = 0; nc < 16; ++nc) {
        float acc2[2][4][4];
#pragma unroll
        for (int mt = 0; mt < 2; ++mt)
#pragma unroll
            for (int j = 0; j < 4; ++j)
#pragma unroll
                for (int q = 0; q < 4; ++q) acc2[mt][j][q] = 0.f;

        const uint32_t bbB = sbu + SM_B0 + (uint32_t)(nc & 1) * B_STRIDE;
#pragma unroll
        for (int kk = 0; kk < 4; ++kk) {
#pragma unroll
            for (int jj = 0; jj < 2; ++jj) {
                uint32_t bh[4];
                uint32_t bo = swz((uint32_t)(s2ng * 32 + jj * 16) * 128 + bpair + kk * 32);
                ldm_x4(bbB + bo, bh);
#pragma unroll
                for (int mt = 0; mt < 2; ++mt) {
                    mma16816(acc2[mt][jj * 2], hf[mt][kk], bh);
                    mma16816(acc2[mt][jj * 2 + 1], hf[mt][kk], bh + 2);
                }
            }
        }

        // epilogue: direct STG.64
        const int nb0 = nc * 128 + s2ng * 32 + 2 * tq;
#pragma unroll
        for (int mt = 0; mt < 2; ++mt)
#pragma unroll
            for (int j = 0; j < 4; ++j) {
                int colo = nb0 + j * 8;
                if (tko[mt][0] >= 0)
                    *(float2*)(out + (size_t)tko[mt][0] * DIM + colo) =
                        make_float2(acc2[mt][j][0], acc2[mt][j][1]);
                if (tko[mt][1] >= 0)
                    *(float2*)(out + (size_t)tko[mt][1] * DIM + colo) =
                        make_float2(acc2[mt][j][2], acc2[mt][j][3]);
            }

        if (nc < 15) {
            STORE_B((nc + 1) & 1);
            if (nc < 14) LOAD_B((nc + 2) * 128);
        }
        __syncthreads();
    }
}

// ---------------- launch ----------------
extern "C" void kernel_launch(void* const* d_in, const int* in_sizes, int n_in,
                              void* d_out, int out_size) {
    const float* x  = (const float*)d_in[0];   // [B,S,D]
    const float* Aw = (const float*)d_in[1];   // [E,R,D]
    const float* Bw = (const float*)d_in[2];   // [E,D,R]
    const int*   ti = (const int*)d_in[3];     // [B,S]
    float* out = (float*)d_out;
    (void)in_sizes; (void)n_in; (void)out_size;

    static int smem_set = 0;
    if (!smem_set) {
        cudaFuncSetAttribute(k_main, cudaFuncAttributeMaxDynamicSharedMemorySize, SMEM_BYTES);
        smem_set = 1;
    }

    k_sort<<<1, 1024>>>(ti);
    dim3 grid(NTOK / TM, E_N, 1);
    k_main<<<grid, NTHR, SMEM_BYTES>>>(x, Aw, Bw, out);
}

// round 13
// speedup vs baseline: 1.7225x; 1.0829x over previous
#include <cuda_runtime.h>
#include <cuda_fp16.h>
#include <cstdint>

// Problem constants (E=8, R=64, B=4, S=4096, D=2048)
#define E_N   8
#define RNK   64
#define DIM   2048
#define NTOK  16384
#define TM    128
#define NTHR  512

// ---------------- device scratch ----------------
__device__ int g_count[E_N];
__device__ int g_offset[E_N];
__device__ int g_tokens[NTOK];

// ---------------- helpers ----------------
__device__ __forceinline__ uint32_t smem_u32(const void* p) {
    uint32_t a;
    asm("{ .reg .u64 t; cvta.to.shared.u64 t, %1; cvt.u32.u64 %0, t; }" : "=r"(a) : "l"(p));
    return a;
}
__device__ __forceinline__ uint32_t swz(uint32_t o) { return o ^ ((o >> 3) & 0x70); }

// pack two fp32 -> fp16x2 (a -> low half, b -> high half)
__device__ __forceinline__ uint32_t pk2(float a, float b) {
    uint32_t r;
    asm("cvt.rn.f16x2.f32 %0, %1, %2;" : "=r"(r) : "f"(b), "f"(a));
    return r;
}

__device__ __forceinline__ void ldm_x4(uint32_t a, uint32_t r[4]) {
    asm volatile("ldmatrix.sync.aligned.m8n8.x4.shared.b16 {%0,%1,%2,%3}, [%4];"
                 : "=r"(r[0]), "=r"(r[1]), "=r"(r[2]), "=r"(r[3]) : "r"(a));
}
__device__ __forceinline__ void mma16816(float* c, const uint32_t* a, const uint32_t* b) {
    asm volatile("mma.sync.aligned.m16n8k16.row.col.f32.f16.f16.f32 "
                 "{%0,%1,%2,%3}, {%4,%5,%6,%7}, {%8,%9}, {%0,%1,%2,%3};"
                 : "+f"(c[0]), "+f"(c[1]), "+f"(c[2]), "+f"(c[3])
                 : "r"(a[0]), "r"(a[1]), "r"(a[2]), "r"(a[3]), "r"(b[0]), "r"(b[1]));
}

// ---------------- SMEM layout (bytes) ----------------
// 64    : tok[128]
// 1024  : X bufs fp16 (128 rows x 128B, swz) 16K each; X0@1024, X1@17408 (end 33792)
//         stage2 B bufs reuse X slots: 16K each; B0@1024, B1@17408
// 33792 : A bufs fp16 8K each; A0@33792, A1@41984 (end 50176)
// 50176 : H fp16 16K (end 66560)
#define SM_TOK    64
#define SM_X0     1024
#define X_STRIDE  16384
#define SM_B0     1024
#define B_STRIDE  16384
#define SM_A0     33792
#define A_STRIDE  8192
#define SM_H      50176
#define SMEM_BYTES 66560

// ---------------- sort kernel: one CTA per expert, no inter-CTA deps ----------------
__global__ void __launch_bounds__(1024) k_sort(const int* __restrict__ ti) {
    const int e = blockIdx.x;
    __shared__ int sc[E_N];
    __shared__ int pos;
    const int tid = threadIdx.x;
    const int lane = tid & 31;
    if (tid < E_N) sc[tid] = 0;
    __syncthreads();
    for (int t = tid; t < NTOK; t += 1024) {
        int v = ti[t];
        unsigned mask = __match_any_sync(0xffffffffu, v);
        if (lane == __ffs(mask) - 1) atomicAdd(&sc[v], __popc(mask));
    }
    __syncthreads();
    if (tid == 0) {
        int off = 0;
        for (int i = 0; i < e; ++i) off += sc[i];
        g_count[e] = sc[e];
        g_offset[e] = off;
        pos = off;
    }
    __syncthreads();
    for (int t = tid; t < NTOK; t += 1024) {
        int v = ti[t];
        bool m = (v == e);
        unsigned bal = __ballot_sync(0xffffffffu, m);
        if (bal) {
            int leader = __ffs(bal) - 1;
            int prior = __popc(bal & ((1u << lane) - 1));
            int basep = 0;
            if (lane == leader) basep = atomicAdd(&pos, __popc(bal));
            basep = __shfl_sync(0xffffffffu, basep, leader);
            if (m) g_tokens[basep + prior] = t;
        }
    }
}

// ---------------- main kernel ----------------
__global__ void __launch_bounds__(NTHR, 1)
k_main(const float* __restrict__ x,
       const float* __restrict__ Aw,
       const float* __restrict__ Bw,
       float* __restrict__ out) {
    const int e = blockIdx.y;
    const int cnt = g_count[e];
    const int mstart = blockIdx.x * TM;
    if (mstart >= cnt) return;
    const int base = g_offset[e];

    extern __shared__ char smc[];
    const uint32_t sbu = smem_u32(smc);
    const int tid = threadIdx.x;
    const int wid = tid >> 5;
    const int lane = tid & 31;
    const int g = lane >> 2;
    const int tq = lane & 3;
    // stage-1 warp tile: m16 x n32
    const int s1mg = wid >> 1;
    const int s1ng = wid & 1;
    // stage-2 warp tile: m32 x n32
    const int s2mg = wid >> 2;
    const int s2ng = wid & 3;
    int* tok = (int*)(smc + SM_TOK);

    if (tid < TM) {
        int i = mstart + tid;
        tok[tid] = (i < cnt) ? g_tokens[base + i] : -1;
    }
    __syncthreads();

    const float* Arow = Aw + (size_t)e * RNK * DIM;
    const float* Brow = Bw + (size_t)e * DIM * RNK;

    // ldmatrix lane patterns (pre-swizzle, relative to tile row base)
    const uint32_t bpair = (uint32_t)((lane & 7) + ((lane >> 4) << 3)) * 128 +
                           (uint32_t)((lane >> 3) & 1) * 16;          // 16-row n-pair
    const uint32_t apat  = (uint32_t)(lane & 15) * 128 + (uint32_t)(lane >> 4) * 16; // m16 A-op

    // ---- fill mappings (coalesced full 128B lines per LDG instr) ----
    const int xfr = tid >> 3, xfq = tid & 7;
    const int xt0 = tok[xfr], xt1 = tok[xfr + 64];
    const float* xp0 = x + (size_t)(xt0 < 0 ? 0 : xt0) * DIM;
    const float* xp1 = x + (size_t)(xt1 < 0 ? 0 : xt1) * DIM;
    float4 vx[4];
    const int fr = tid >> 3, fq = tid & 7;
    float4 va[2];

#define LOAD_X(K0)                                                              \
    do {                                                                        \
        float4 z = make_float4(0.f, 0.f, 0.f, 0.f);                             \
        vx[0] = (xt0 >= 0) ? *(const float4*)(xp0 + (K0) + xfq * 4) : z;        \
        vx[1] = (xt0 >= 0) ? *(const float4*)(xp0 + (K0) + 32 + xfq * 4) : z;   \
        vx[2] = (xt1 >= 0) ? *(const float4*)(xp1 + (K0) + xfq * 4) : z;        \
        vx[3] = (xt1 >= 0) ? *(const float4*)(xp1 + (K0) + 32 + xfq * 4) : z;   \
    } while (0)

#define STORE_X(BUF)                                                            \
    do {                                                                        \
        char* xb_ = smc + SM_X0 + (BUF) * X_STRIDE;                             \
        *(uint2*)(xb_ + swz((uint32_t)xfr * 128 + xfq * 8)) =                   \
            make_uint2(pk2(vx[0].x, vx[0].y), pk2(vx[0].z, vx[0].w));           \
        *(uint2*)(xb_ + swz((uint32_t)xfr * 128 + 64 + xfq * 8)) =              \
            make_uint2(pk2(vx[1].x, vx[1].y), pk2(vx[1].z, vx[1].w));           \
        *(uint2*)(xb_ + swz((uint32_t)(xfr + 64) * 128 + xfq * 8)) =            \
            make_uint2(pk2(vx[2].x, vx[2].y), pk2(vx[2].z, vx[2].w));           \
        *(uint2*)(xb_ + swz((uint32_t)(xfr + 64) * 128 + 64 + xfq * 8)) =       \
            make_uint2(pk2(vx[3].x, vx[3].y), pk2(vx[3].z, vx[3].w));           \
    } while (0)

#define LOAD_A(K0)                                                              \
    do {                                                                        \
        _Pragma("unroll") for (int i = 0; i < 2; ++i) va[i] =                   \
            *(const float4*)(Arow + (size_t)fr * DIM + (K0) + fq * 4 + i * 32); \
    } while (0)

#define STORE_A(BUF)                                                            \
    do {                                                                        \
        char* ah = smc + SM_A0 + (BUF) * A_STRIDE;                              \
        _Pragma("unroll") for (int i = 0; i < 2; ++i) {                         \
            uint32_t p0 = pk2(va[i].x, va[i].y);                                \
            uint32_t p1 = pk2(va[i].z, va[i].w);                                \
            uint32_t off = swz((uint32_t)fr * 128 + fq * 8 + i * 64);           \
            *(uint2*)(ah + off) = make_uint2(p0, p1);                           \
        }                                                                       \
    } while (0)

    // ===== stage 1: H[128,64] = X[128,2048] * A_e^T =====
    float acc1[4][4];
#pragma unroll
    for (int j = 0; j < 4; ++j)
#pragma unroll
        for (int q = 0; q < 4; ++q) acc1[j][q] = 0.f;

    LOAD_X(0);
    LOAD_A(0);
    STORE_X(0);
    STORE_A(0);
    __syncthreads();
    LOAD_X(64);
    LOAD_A(64);

    for (int c = 0; c < 32; ++c) {
        const uint32_t xbB = sbu + SM_X0 + (uint32_t)(c & 1) * X_STRIDE;
        const uint32_t ahB = sbu + SM_A0 + (uint32_t)(c & 1) * A_STRIDE;
#pragma unroll
        for (int kk = 0; kk < 4; ++kk) {
            uint32_t xf[4];
            uint32_t xo = swz((uint32_t)(s1mg * 16) * 128 + apat + kk * 32);
            ldm_x4(xbB + xo, xf);
#pragma unroll
            for (int jj = 0; jj < 2; ++jj) {
                uint32_t bh[4];
                uint32_t ao = swz((uint32_t)(s1ng * 32 + jj * 16) * 128 + bpair + kk * 32);
                ldm_x4(ahB + ao, bh);
                mma16816(acc1[jj * 2], xf, bh);
                mma16816(acc1[jj * 2 + 1], xf, bh + 2);
            }
        }
        if (c < 31) {
            STORE_X((c + 1) & 1);
            STORE_A((c + 1) & 1);
            if (c < 30) {
                LOAD_X((c + 2) * 64);
                LOAD_A((c + 2) * 64);
            }
        }
        __syncthreads();
    }

    // ===== stage 2 fills (B): 128n x 64r fp32 per chunk =====
    // Rows are PERMUTED within each 16-block: actual n16 -> smem row (n16&1)*8 + (n16>>1),
    // so MMA tile0 col c = actual 2c, tile1 col c = actual 2c+1 (epilogue gets 4 contiguous n).
    const int bfn = tid >> 3, bfq = tid & 7;
    float4 vb[4];

#define LOAD_B(N0)                                                              \
    do {                                                                        \
        const float* s0 = Brow + (size_t)((N0) + bfn) * RNK + bfq * 4;          \
        const float* s1 = Brow + (size_t)((N0) + bfn + 64) * RNK + bfq * 4;     \
        vb[0] = *(const float4*)(s0);                                           \
        vb[1] = *(const float4*)(s0 + 32);                                      \
        vb[2] = *(const float4*)(s1);                                           \
        vb[3] = *(const float4*)(s1 + 32);                                      \
    } while (0)

#define STORE_B(BUF)                                                            \
    do {                                                                        \
        char* bh_ = smc + SM_B0 + (BUF) * B_STRIDE;                             \
        _Pragma("unroll") for (int i = 0; i < 4; ++i) {                         \
            uint32_t p0 = pk2(vb[i].x, vb[i].y);                                \
            uint32_t p1 = pk2(vb[i].z, vb[i].w);                                \
            uint32_t r_ = (uint32_t)bfn + (i >> 1) * 64;                        \
            uint32_t n16_ = r_ & 15u;                                           \
            uint32_t rs_ = (r_ & ~15u) + ((n16_ & 1u) << 3) + (n16_ >> 1);      \
            uint32_t off = swz(rs_ * 128 + bfq * 8 + (i & 1) * 64);             \
            *(uint2*)(bh_ + off) = make_uint2(p0, p1);                          \
        }                                                                       \
    } while (0)

    LOAD_B(0);   // start GMEM reads early

    // ===== H -> SMEM fp16 (fragment-consistent layout) =====
    {
        char* hh = smc + SM_H;
#pragma unroll
        for (int j = 0; j < 4; ++j) {
            int col = s1ng * 32 + j * 8 + 2 * tq;
            int r0 = s1mg * 16 + g;
            uint32_t p0 = pk2(acc1[j][0], acc1[j][1]);
            *(uint32_t*)(hh + swz((uint32_t)r0 * 128 + (uint32_t)col * 2)) = p0;
            uint32_t p1 = pk2(acc1[j][2], acc1[j][3]);
            *(uint32_t*)(hh + swz((uint32_t)(r0 + 8) * 128 + (uint32_t)col * 2)) = p1;
        }
    }
    STORE_B(0);
    __syncthreads();

    // preload ALL H fragments into registers (reused across all 16 n-chunks)
    uint32_t hf[2][4][4];
#pragma unroll
    for (int mt = 0; mt < 2; ++mt)
#pragma unroll
        for (int kk = 0; kk < 4; ++kk) {
            uint32_t ho = swz((uint32_t)(s2mg * 32 + mt * 16) * 128 + apat + kk * 32);
            ldm_x4(sbu + SM_H + ho, hf[mt][kk]);
        }

    // stage-2 output tokens for this warp
    int tko[2][2];
#pragma unroll
    for (int mt = 0; mt < 2; ++mt) {
        tko[mt][0] = tok[s2mg * 32 + mt * 16 + g];
        tko[mt][1] = tok[s2mg * 32 + mt * 16 + 8 + g];
    }

    LOAD_B(128);

    // ===== stage 2: O[128,2048] = H[128,64] * B_e^T, 16 n-chunks of 128 =====
    for (int nc = 0; nc < 16; ++nc) {
        float acc2[2][4][4];
#pragma unroll
        for (int mt = 0; mt < 2; ++mt)
#pragma unroll
            for (int j = 0; j < 4; ++j)
#pragma unroll
                for (int q = 0; q < 4; ++q) acc2[mt][j][q] = 0.f;

        const uint32_t bbB = sbu + SM_B0 + (uint32_t)(nc & 1) * B_STRIDE;
#pragma unroll
        for (int kk = 0; kk < 4; ++kk) {
#pragma unroll
            for (int jj = 0; jj < 2; ++jj) {
                uint32_t bh[4];
                uint32_t bo = swz((uint32_t)(s2ng * 32 + jj * 16) * 128 + bpair + kk * 32);
                ldm_x4(bbB + bo, bh);
#pragma unroll
                for (int mt = 0; mt < 2; ++mt) {
                    mma16816(acc2[mt][jj * 2], hf[mt][kk], bh);
                    mma16816(acc2[mt][jj * 2 + 1], hf[mt][kk], bh + 2);
                }
            }
        }

        // epilogue: STG.128, 4 contiguous cols per thread (via B permutation)
        const int nb0 = nc * 128 + s2ng * 32 + 4 * tq;
#pragma unroll
        for (int mt = 0; mt < 2; ++mt)
#pragma unroll
            for (int jj = 0; jj < 2; ++jj) {
                int colo = nb0 + jj * 16;
                float* t0 = acc2[mt][jj * 2];
                float* t1 = acc2[mt][jj * 2 + 1];
                if (tko[mt][0] >= 0)
                    *(float4*)(out + (size_t)tko[mt][0] * DIM + colo) =
                        make_float4(t0[0], t1[0], t0[1], t1[1]);
                if (tko[mt][1] >= 0)
                    *(float4*)(out + (size_t)tko[mt][1] * DIM + colo) =
                        make_float4(t0[2], t1[2], t0[3], t1[3]);
            }

        if (nc < 15) {
            STORE_B((nc + 1) & 1);
            if (nc < 14) LOAD_B((nc + 2) * 128);
        }
        __syncthreads();
    }
}

// ---------------- launch ----------------
extern "C" void kernel_launch(void* const* d_in, const int* in_sizes, int n_in,
                              void* d_out, int out_size) {
    const float* x  = (const float*)d_in[0];   // [B,S,D]
    const float* Aw = (const float*)d_in[1];   // [E,R,D]
    const float* Bw = (const float*)d_in[2];   // [E,D,R]
    const int*   ti = (const int*)d_in[3];     // [B,S]
    float* out = (float*)d_out;
    (void)in_sizes; (void)n_in; (void)out_size;

    static int smem_set = 0;
    if (!smem_set) {
        cudaFuncSetAttribute(k_main, cudaFuncAttributeMaxDynamicSharedMemorySize, SMEM_BYTES);
        smem_set = 1;
    }

    k_sort<<<E_N, 1024>>>(ti);
    dim3 grid(NTOK / TM, E_N, 1);
    k_main<<<grid, NTHR, SMEM_BYTES>>>(x, Aw, Bw, out);
}

// round 14
// speedup vs baseline: 1.7646x; 1.0245x over previous
#include <cuda_runtime.h>
#include <cuda_fp16.h>
#include <cstdint>

// Problem constants (E=8, R=64, B=4, S=4096, D=2048)
#define E_N   8
#define RNK   64
#define DIM   2048
#define NTOK  16384
#define TM    128
#define NTHR  512

// ---------------- device scratch ----------------
__device__ int g_count[E_N];
__device__ int g_offset[E_N];
__device__ int g_tokens[NTOK];

// ---------------- helpers ----------------
__device__ __forceinline__ uint32_t smem_u32(const void* p) {
    uint32_t a;
    asm("{ .reg .u64 t; cvta.to.shared.u64 t, %1; cvt.u32.u64 %0, t; }" : "=r"(a) : "l"(p));
    return a;
}
__device__ __forceinline__ uint32_t swz(uint32_t o) { return o ^ ((o >> 3) & 0x70); }

// pack two fp32 -> fp16x2 (a -> low half, b -> high half)
__device__ __forceinline__ uint32_t pk2(float a, float b) {
    uint32_t r;
    asm("cvt.rn.f16x2.f32 %0, %1, %2;" : "=r"(r) : "f"(b), "f"(a));
    return r;
}

__device__ __forceinline__ void ldm_x4(uint32_t a, uint32_t r[4]) {
    asm volatile("ldmatrix.sync.aligned.m8n8.x4.shared.b16 {%0,%1,%2,%3}, [%4];"
                 : "=r"(r[0]), "=r"(r[1]), "=r"(r[2]), "=r"(r[3]) : "r"(a));
}
__device__ __forceinline__ void mma16816(float* c, const uint32_t* a, const uint32_t* b) {
    asm volatile("mma.sync.aligned.m16n8k16.row.col.f32.f16.f16.f32 "
                 "{%0,%1,%2,%3}, {%4,%5,%6,%7}, {%8,%9}, {%0,%1,%2,%3};"
                 : "+f"(c[0]), "+f"(c[1]), "+f"(c[2]), "+f"(c[3])
                 : "r"(a[0]), "r"(a[1]), "r"(a[2]), "r"(a[3]), "r"(b[0]), "r"(b[1]));
}

// ---------------- SMEM layout (bytes) ----------------
// 64    : tok[128]
// 1024  : X bufs fp16 (128 rows x 128B, swz) 16K x4; X0..X3 @1024+16K*i (end 66560)
//         stage2 B bufs reuse X region: 16K x4 @ same slots
// 66560 : A bufs fp16 8K x4; A0..A3 @66560+8K*i (end 99328)
// 99328 : H fp16 16K (end 115712)
#define SM_TOK    64
#define SM_X0     1024
#define X_STRIDE  16384
#define SM_B0     1024
#define B_STRIDE  16384
#define SM_A0     66560
#define A_STRIDE  8192
#define SM_H      99328
#define SMEM_BYTES 115712

// ---------------- sort kernel: one CTA per expert, no inter-CTA deps ----------------
__global__ void __launch_bounds__(1024) k_sort(const int* __restrict__ ti) {
    const int e = blockIdx.x;
    __shared__ int sc[E_N];
    __shared__ int pos;
    const int tid = threadIdx.x;
    const int lane = tid & 31;
    if (tid < E_N) sc[tid] = 0;
    __syncthreads();
    for (int t = tid; t < NTOK; t += 1024) {
        int v = ti[t];
        unsigned mask = __match_any_sync(0xffffffffu, v);
        if (lane == __ffs(mask) - 1) atomicAdd(&sc[v], __popc(mask));
    }
    __syncthreads();
    if (tid == 0) {
        int off = 0;
        for (int i = 0; i < e; ++i) off += sc[i];
        g_count[e] = sc[e];
        g_offset[e] = off;
        pos = off;
    }
    __syncthreads();
    for (int t = tid; t < NTOK; t += 1024) {
        int v = ti[t];
        bool m = (v == e);
        unsigned bal = __ballot_sync(0xffffffffu, m);
        if (bal) {
            int leader = __ffs(bal) - 1;
            int prior = __popc(bal & ((1u << lane) - 1));
            int basep = 0;
            if (lane == leader) basep = atomicAdd(&pos, __popc(bal));
            basep = __shfl_sync(0xffffffffu, basep, leader);
            if (m) g_tokens[basep + prior] = t;
        }
    }
}

// ---------------- main kernel ----------------
__global__ void __launch_bounds__(NTHR, 1)
k_main(const float* __restrict__ x,
       const float* __restrict__ Aw,
       const float* __restrict__ Bw,
       float* __restrict__ out) {
    const int e = blockIdx.y;
    const int cnt = g_count[e];
    const int mstart = blockIdx.x * TM;
    if (mstart >= cnt) return;
    const int base = g_offset[e];

    extern __shared__ char smc[];
    const uint32_t sbu = smem_u32(smc);
    const int tid = threadIdx.x;
    const int wid = tid >> 5;
    const int lane = tid & 31;
    const int g = lane >> 2;
    const int tq = lane & 3;
    // stage-1 warp tile: m16 x n32
    const int s1mg = wid >> 1;
    const int s1ng = wid & 1;
    // stage-2 warp tile: m32 x n32
    const int s2mg = wid >> 2;
    const int s2ng = wid & 3;
    int* tok = (int*)(smc + SM_TOK);

    if (tid < TM) {
        int i = mstart + tid;
        tok[tid] = (i < cnt) ? g_tokens[base + i] : -1;
    }
    __syncthreads();

    const float* Arow = Aw + (size_t)e * RNK * DIM;
    const float* Brow = Bw + (size_t)e * DIM * RNK;

    // ldmatrix lane patterns (pre-swizzle, relative to tile row base)
    const uint32_t bpair = (uint32_t)((lane & 7) + ((lane >> 4) << 3)) * 128 +
                           (uint32_t)((lane >> 3) & 1) * 16;          // 16-row n-pair
    const uint32_t apat  = (uint32_t)(lane & 15) * 128 + (uint32_t)(lane >> 4) * 16; // m16 A-op

    // ---- fill mappings (coalesced full 128B lines per LDG instr) ----
    const int xfr = tid >> 3, xfq = tid & 7;
    const int xt0 = tok[xfr], xt1 = tok[xfr + 64];
    const float* xp0 = x + (size_t)(xt0 < 0 ? 0 : xt0) * DIM;
    const float* xp1 = x + (size_t)(xt1 < 0 ? 0 : xt1) * DIM;
    float4 vx[4];
    const int fr = tid >> 3, fq = tid & 7;
    float4 va[2];

#define LOAD_X(K0)                                                              \
    do {                                                                        \
        float4 z = make_float4(0.f, 0.f, 0.f, 0.f);                             \
        vx[0] = (xt0 >= 0) ? *(const float4*)(xp0 + (K0) + xfq * 4) : z;        \
        vx[1] = (xt0 >= 0) ? *(const float4*)(xp0 + (K0) + 32 + xfq * 4) : z;   \
        vx[2] = (xt1 >= 0) ? *(const float4*)(xp1 + (K0) + xfq * 4) : z;        \
        vx[3] = (xt1 >= 0) ? *(const float4*)(xp1 + (K0) + 32 + xfq * 4) : z;   \
    } while (0)

#define STORE_X(BUF)                                                            \
    do {                                                                        \
        char* xb_ = smc + SM_X0 + (BUF) * X_STRIDE;                             \
        *(uint2*)(xb_ + swz((uint32_t)xfr * 128 + xfq * 8)) =                   \
            make_uint2(pk2(vx[0].x, vx[0].y), pk2(vx[0].z, vx[0].w));           \
        *(uint2*)(xb_ + swz((uint32_t)xfr * 128 + 64 + xfq * 8)) =              \
            make_uint2(pk2(vx[1].x, vx[1].y), pk2(vx[1].z, vx[1].w));           \
        *(uint2*)(xb_ + swz((uint32_t)(xfr + 64) * 128 + xfq * 8)) =            \
            make_uint2(pk2(vx[2].x, vx[2].y), pk2(vx[2].z, vx[2].w));           \
        *(uint2*)(xb_ + swz((uint32_t)(xfr + 64) * 128 + 64 + xfq * 8)) =       \
            make_uint2(pk2(vx[3].x, vx[3].y), pk2(vx[3].z, vx[3].w));           \
    } while (0)

#define LOAD_A(K0)                                                              \
    do {                                                                        \
        _Pragma("unroll") for (int i = 0; i < 2; ++i) va[i] =                   \
            *(const float4*)(Arow + (size_t)fr * DIM + (K0) + fq * 4 + i * 32); \
    } while (0)

#define STORE_A(BUF)                                                            \
    do {                                                                        \
        char* ah = smc + SM_A0 + (BUF) * A_STRIDE;                              \
        _Pragma("unroll") for (int i = 0; i < 2; ++i) {                         \
            uint32_t p0 = pk2(va[i].x, va[i].y);                                \
            uint32_t p1 = pk2(va[i].z, va[i].w);                                \
            uint32_t off = swz((uint32_t)fr * 128 + fq * 8 + i * 64);           \
            *(uint2*)(ah + off) = make_uint2(p0, p1);                           \
        }                                                                       \
    } while (0)

    // ===== stage 1: H[128,64] = X[128,2048] * A_e^T =====
    float acc1[4][4];
#pragma unroll
    for (int j = 0; j < 4; ++j)
#pragma unroll
        for (int q = 0; q < 4; ++q) acc1[j][q] = 0.f;

    // prologue: fill bufs 0,1; regs hold chunk 2
    LOAD_X(0);
    LOAD_A(0);
    STORE_X(0);
    STORE_A(0);
    LOAD_X(64);
    LOAD_A(64);
    STORE_X(1);
    STORE_A(1);
    LOAD_X(128);
    LOAD_A(128);
    __syncthreads();

    for (int c = 0; c < 32; ++c) {
        const uint32_t xbB = sbu + SM_X0 + (uint32_t)(c & 3) * X_STRIDE;
        const uint32_t ahB = sbu + SM_A0 + (uint32_t)(c & 3) * A_STRIDE;
#pragma unroll
        for (int kk = 0; kk < 4; ++kk) {
            uint32_t xf[4];
            uint32_t xo = swz((uint32_t)(s1mg * 16) * 128 + apat + kk * 32);
            ldm_x4(xbB + xo, xf);
#pragma unroll
            for (int jj = 0; jj < 2; ++jj) {
                uint32_t bh[4];
                uint32_t ao = swz((uint32_t)(s1ng * 32 + jj * 16) * 128 + bpair + kk * 32);
                ldm_x4(ahB + ao, bh);
                mma16816(acc1[jj * 2], xf, bh);
                mma16816(acc1[jj * 2 + 1], xf, bh + 2);
            }
        }
        if (c < 30) {
            STORE_X((c + 2) & 3);
            STORE_A((c + 2) & 3);
        }
        if (c < 29) {
            LOAD_X((c + 3) * 64);
            LOAD_A((c + 3) * 64);
        }
        if (c & 1) __syncthreads();
    }

    // ===== stage 2 fills (B): 128n x 64r fp32 per chunk =====
    // Rows PERMUTED within each 16-block: n16 -> (n16&1)*8 + (n16>>1) so the two
    // n8 MMA tiles interleave -> epilogue writes 4 contiguous n per thread.
    const int bfn = tid >> 3, bfq = tid & 7;
    float4 vb[4];

#define LOAD_B(N0)                                                              \
    do {                                                                        \
        const float* s0 = Brow + (size_t)((N0) + bfn) * RNK + bfq * 4;          \
        const float* s1 = Brow + (size_t)((N0) + bfn + 64) * RNK + bfq * 4;     \
        vb[0] = *(const float4*)(s0);                                           \
        vb[1] = *(const float4*)(s0 + 32);                                      \
        vb[2] = *(const float4*)(s1);                                           \
        vb[3] = *(const float4*)(s1 + 32);                                      \
    } while (0)

#define STORE_B(BUF)                                                            \
    do {                                                                        \
        char* bh_ = smc + SM_B0 + (BUF) * B_STRIDE;                             \
        _Pragma("unroll") for (int i = 0; i < 4; ++i) {                         \
            uint32_t p0 = pk2(vb[i].x, vb[i].y);                                \
            uint32_t p1 = pk2(vb[i].z, vb[i].w);                                \
            uint32_t r_ = (uint32_t)bfn + (i >> 1) * 64;                        \
            uint32_t n16_ = r_ & 15u;                                           \
            uint32_t rs_ = (r_ & ~15u) + ((n16_ & 1u) << 3) + (n16_ >> 1);      \
            uint32_t off = swz(rs_ * 128 + bfq * 8 + (i & 1) * 64);             \
            *(uint2*)(bh_ + off) = make_uint2(p0, p1);                          \
        }                                                                       \
    } while (0)

    LOAD_B(0);   // start GMEM reads early (X region safe: synced after c=31)

    // ===== H -> SMEM fp16 (fragment-consistent layout) =====
    {
        char* hh = smc + SM_H;
#pragma unroll
        for (int j = 0; j < 4; ++j) {
            int col = s1ng * 32 + j * 8 + 2 * tq;
            int r0 = s1mg * 16 + g;
            uint32_t p0 = pk2(acc1[j][0], acc1[j][1]);
            *(uint32_t*)(hh + swz((uint32_t)r0 * 128 + (uint32_t)col * 2)) = p0;
            uint32_t p1 = pk2(acc1[j][2], acc1[j][3]);
            *(uint32_t*)(hh + swz((uint32_t)(r0 + 8) * 128 + (uint32_t)col * 2)) = p1;
        }
    }
    STORE_B(0);
    LOAD_B(128);
    STORE_B(1);
    LOAD_B(256);
    __syncthreads();

    // preload ALL H fragments into registers (reused across all 16 n-chunks)
    uint32_t hf[2][4][4];
#pragma unroll
    for (int mt = 0; mt < 2; ++mt)
#pragma unroll
        for (int kk = 0; kk < 4; ++kk) {
            uint32_t ho = swz((uint32_t)(s2mg * 32 + mt * 16) * 128 + apat + kk * 32);
            ldm_x4(sbu + SM_H + ho, hf[mt][kk]);
        }

    // stage-2 output tokens for this warp
    int tko[2][2];
#pragma unroll
    for (int mt = 0; mt < 2; ++mt) {
        tko[mt][0] = tok[s2mg * 32 + mt * 16 + g];
        tko[mt][1] = tok[s2mg * 32 + mt * 16 + 8 + g];
    }

    // ===== stage 2: O[128,2048] = H[128,64] * B_e^T, 16 n-chunks of 128 =====
    for (int nc = 0; nc < 16; ++nc) {
        float acc2[2][4][4];
#pragma unroll
        for (int mt = 0; mt < 2; ++mt)
#pragma unroll
            for (int j = 0; j < 4; ++j)
#pragma unroll
                for (int q = 0; q < 4; ++q) acc2[mt][j][q] = 0.f;

        const uint32_t bbB = sbu + SM_B0 + (uint32_t)(nc & 3) * B_STRIDE;
#pragma unroll
        for (int kk = 0; kk < 4; ++kk) {
#pragma unroll
            for (int jj = 0; jj < 2; ++jj) {
                uint32_t bh[4];
                uint32_t bo = swz((uint32_t)(s2ng * 32 + jj * 16) * 128 + bpair + kk * 32);
                ldm_x4(bbB + bo, bh);
#pragma unroll
                for (int mt = 0; mt < 2; ++mt) {
                    mma16816(acc2[mt][jj * 2], hf[mt][kk], bh);
                    mma16816(acc2[mt][jj * 2 + 1], hf[mt][kk], bh + 2);
                }
            }
        }

        // epilogue: STG.128 evict-first, 4 contiguous cols per thread
        const int nb0 = nc * 128 + s2ng * 32 + 4 * tq;
#pragma unroll
        for (int mt = 0; mt < 2; ++mt)
#pragma unroll
            for (int jj = 0; jj < 2; ++jj) {
                int colo = nb0 + jj * 16;
                float* t0 = acc2[mt][jj * 2];
                float* t1 = acc2[mt][jj * 2 + 1];
                if (tko[mt][0] >= 0)
                    __stcs((float4*)(out + (size_t)tko[mt][0] * DIM + colo),
                           make_float4(t0[0], t1[0], t0[1], t1[1]));
                if (tko[mt][1] >= 0)
                    __stcs((float4*)(out + (size_t)tko[mt][1] * DIM + colo),
                           make_float4(t0[2], t1[2], t0[3], t1[3]));
            }

        if (nc < 14) STORE_B((nc + 2) & 3);
        if (nc < 13) LOAD_B((nc + 3) * 128);
        if (nc & 1) __syncthreads();
    }
}

// ---------------- launch ----------------
extern "C" void kernel_launch(void* const* d_in, const int* in_sizes, int n_in,
                              void* d_out, int out_size) {
    const float* x  = (const float*)d_in[0];   // [B,S,D]
    const float* Aw = (const float*)d_in[1];   // [E,R,D]
    const float* Bw = (const float*)d_in[2];   // [E,D,R]
    const int*   ti = (const int*)d_in[3];     // [B,S]
    float* out = (float*)d_out;
    (void)in_sizes; (void)n_in; (void)out_size;

    static int smem_set = 0;
    if (!smem_set) {
        cudaFuncSetAttribute(k_main, cudaFuncAttributeMaxDynamicSharedMemorySize, SMEM_BYTES);
        smem_set = 1;
    }

    k_sort<<<E_N, 1024>>>(ti);
    dim3 grid(NTOK / TM, E_N, 1);
    k_main<<<grid, NTHR, SMEM_BYTES>>>(x, Aw, Bw, out);
}

// round 16
// speedup vs baseline: 1.9334x; 1.0956x over previous
#include <cuda_runtime.h>
#include <cuda_fp16.h>
#include <cstdint>

// Problem constants (E=8, R=64, B=4, S=4096, D=2048)
#define E_N   8
#define RNK   64
#define DIM   2048
#define NTOK  16384
#define TM    128
#define NTHR  512

// ---------------- device scratch ----------------
__device__ int g_count[E_N];
__device__ int g_offset[E_N];
__device__ int g_tokens[NTOK];

// ---------------- helpers ----------------
__device__ __forceinline__ uint32_t smem_u32(const void* p) {
    uint32_t a;
    asm("{ .reg .u64 t; cvta.to.shared.u64 t, %1; cvt.u32.u64 %0, t; }" : "=r"(a) : "l"(p));
    return a;
}
__device__ __forceinline__ uint32_t swz(uint32_t o) { return o ^ ((o >> 3) & 0x70); }

// pack two fp32 -> fp16x2 (a -> low half, b -> high half)
__device__ __forceinline__ uint32_t pk2(float a, float b) {
    uint32_t r;
    asm("cvt.rn.f16x2.f32 %0, %1, %2;" : "=r"(r) : "f"(b), "f"(a));
    return r;
}

__device__ __forceinline__ void ldm_x4(uint32_t a, uint32_t r[4]) {
    asm volatile("ldmatrix.sync.aligned.m8n8.x4.shared.b16 {%0,%1,%2,%3}, [%4];"
                 : "=r"(r[0]), "=r"(r[1]), "=r"(r[2]), "=r"(r[3]) : "r"(a));
}
__device__ __forceinline__ void mma16816(float* c, const uint32_t* a, const uint32_t* b) {
    asm volatile("mma.sync.aligned.m16n8k16.row.col.f32.f16.f16.f32 "
                 "{%0,%1,%2,%3}, {%4,%5,%6,%7}, {%8,%9}, {%0,%1,%2,%3};"
                 : "+f"(c[0]), "+f"(c[1]), "+f"(c[2]), "+f"(c[3])
                 : "r"(a[0]), "r"(a[1]), "r"(a[2]), "r"(a[3]), "r"(b[0]), "r"(b[1]));
}

// ---------------- SMEM layout (bytes) ----------------
// 64    : tok[128]
// 1024  : X bufs fp16 (128 rows x 128B, swz) 16K x4; X0..X3 (end 66560)
//         stage2 B bufs reuse X region: 16K x4 @ same slots
// 66560 : A bufs fp16 8K x4 (end 99328)
// 99328 : H fp16 16K (end 115712)
#define SM_TOK    64
#define SM_X0     1024
#define X_STRIDE  16384
#define SM_B0     1024
#define B_STRIDE  16384
#define SM_A0     66560
#define A_STRIDE  8192
#define SM_H      99328
#define SMEM_BYTES 115712

// ---------------- sort kernel: one CTA per expert, atomic-free rank/scatter ----------------
__global__ void __launch_bounds__(1024) k_sort(const int* __restrict__ ti) {
    const int e = blockIdx.x;
    __shared__ int wc[32];
    __shared__ int wl[32];
    __shared__ int s_base, s_cnt;
    const int tid = threadIdx.x;
    const int lane = tid & 31;
    const int warp = tid >> 5;
    int v[16];
    const int t0 = tid * 16;
#pragma unroll
    for (int i = 0; i < 16; ++i) v[i] = ti[t0 + i];
    int c = 0, lt = 0;
#pragma unroll
    for (int i = 0; i < 16; ++i) {
        c += (v[i] == e);
        lt += (v[i] < e);
    }
    // warp inclusive scan of c; warp reduce of lt
    int pre = c;
#pragma unroll
    for (int d = 1; d < 32; d <<= 1) {
        int y = __shfl_up_sync(0xffffffffu, pre, d);
        if (lane >= d) pre += y;
    }
    int l = lt;
#pragma unroll
    for (int d = 16; d; d >>= 1) l += __shfl_xor_sync(0xffffffffu, l, d);
    if (lane == 31) {
        wc[warp] = pre;
        wl[warp] = l;
    }
    __syncthreads();
    if (warp == 0) {
        int wcv = wc[lane];
        int wpre = wcv;
#pragma unroll
        for (int d = 1; d < 32; d <<= 1) {
            int y = __shfl_up_sync(0xffffffffu, wpre, d);
            if (lane >= d) wpre += y;
        }
        int tl = wl[lane];
#pragma unroll
        for (int d = 16; d; d >>= 1) tl += __shfl_xor_sync(0xffffffffu, tl, d);
        wc[lane] = wpre - wcv;   // exclusive warp offsets
        if (lane == 31) {
            s_base = tl;         // total (< e) = offset of expert e
            s_cnt = wpre;        // total (== e)
        }
    }
    __syncthreads();
    int mybase = s_base + wc[warp] + (pre - c);
#pragma unroll
    for (int i = 0; i < 16; ++i)
        if (v[i] == e) g_tokens[mybase++] = t0 + i;
    if (tid == 0) {
        g_offset[e] = s_base;
        g_count[e] = s_cnt;
    }
}

// ---------------- main kernel ----------------
__global__ void __launch_bounds__(NTHR, 1)
k_main(const float* __restrict__ x,
       const float* __restrict__ Aw,
       const float* __restrict__ Bw,
       float* __restrict__ out) {
    const int e = blockIdx.y;
    const int cnt = g_count[e];
    const int mstart = blockIdx.x * TM;
    if (mstart >= cnt) return;
    const int base = g_offset[e];

    extern __shared__ char smc[];
    const uint32_t sbu = smem_u32(smc);
    const int tid = threadIdx.x;
    const int wid = tid >> 5;
    const int lane = tid & 31;
    const int g = lane >> 2;
    const int tq = lane & 3;
    // stage-1 warp tile: m16 x n32
    const int s1mg = wid >> 1;
    const int s1ng = wid & 1;
    // stage-2 warp tile: m32 x n32
    const int s2mg = wid >> 2;
    const int s2ng = wid & 3;
    int* tok = (int*)(smc + SM_TOK);

    if (tid < TM) {
        int i = mstart + tid;
        tok[tid] = (i < cnt) ? g_tokens[base + i] : -1;
    }
    __syncthreads();

    const float* Arow = Aw + (size_t)e * RNK * DIM;
    const float* Brow = Bw + (size_t)e * DIM * RNK;

    // ldmatrix lane patterns (pre-swizzle, relative to tile row base)
    const uint32_t bpair = (uint32_t)((lane & 7) + ((lane >> 4) << 3)) * 128 +
                           (uint32_t)((lane >> 3) & 1) * 16;          // 16-row n-pair
    const uint32_t apat  = (uint32_t)(lane & 15) * 128 + (uint32_t)(lane >> 4) * 16; // m16 A-op

    // ---- fill mappings (coalesced full 128B lines per LDG instr) ----
    const int xfr = tid >> 3, xfq = tid & 7;
    const int xt0 = tok[xfr], xt1 = tok[xfr + 64];
    const float* xp0 = x + (size_t)(xt0 < 0 ? 0 : xt0) * DIM;
    const float* xp1 = x + (size_t)(xt1 < 0 ? 0 : xt1) * DIM;
    float4 vx[4];
    const int fr = tid >> 3, fq = tid & 7;
    float4 va[2];

#define LOAD_X(K0)                                                              \
    do {                                                                        \
        float4 z = make_float4(0.f, 0.f, 0.f, 0.f);                             \
        vx[0] = (xt0 >= 0) ? *(const float4*)(xp0 + (K0) + xfq * 4) : z;        \
        vx[1] = (xt0 >= 0) ? *(const float4*)(xp0 + (K0) + 32 + xfq * 4) : z;   \
        vx[2] = (xt1 >= 0) ? *(const float4*)(xp1 + (K0) + xfq * 4) : z;        \
        vx[3] = (xt1 >= 0) ? *(const float4*)(xp1 + (K0) + 32 + xfq * 4) : z;   \
    } while (0)

#define STORE_X(BUF)                                                            \
    do {                                                                        \
        char* xb_ = smc + SM_X0 + (BUF) * X_STRIDE;                             \
        *(uint2*)(xb_ + swz((uint32_t)xfr * 128 + xfq * 8)) =                   \
            make_uint2(pk2(vx[0].x, vx[0].y), pk2(vx[0].z, vx[0].w));           \
        *(uint2*)(xb_ + swz((uint32_t)xfr * 128 + 64 + xfq * 8)) =              \
            make_uint2(pk2(vx[1].x, vx[1].y), pk2(vx[1].z, vx[1].w));           \
        *(uint2*)(xb_ + swz((uint32_t)(xfr + 64) * 128 + xfq * 8)) =            \
            make_uint2(pk2(vx[2].x, vx[2].y), pk2(vx[2].z, vx[2].w));           \
        *(uint2*)(xb_ + swz((uint32_t)(xfr + 64) * 128 + 64 + xfq * 8)) =       \
            make_uint2(pk2(vx[3].x, vx[3].y), pk2(vx[3].z, vx[3].w));           \
    } while (0)

#define LOAD_A(K0)                                                              \
    do {                                                                        \
        _Pragma("unroll") for (int i = 0; i < 2; ++i) va[i] =                   \
            *(const float4*)(Arow + (size_t)fr * DIM + (K0) + fq * 4 + i * 32); \
    } while (0)

#define STORE_A(BUF)                                                            \
    do {                                                                        \
        char* ah = smc + SM_A0 + (BUF) * A_STRIDE;                              \
        _Pragma("unroll") for (int i = 0; i < 2; ++i) {                         \
            uint32_t p0 = pk2(va[i].x, va[i].y);                                \
            uint32_t p1 = pk2(va[i].z, va[i].w);                                \
            uint32_t off = swz((uint32_t)fr * 128 + fq * 8 + i * 64);           \
            *(uint2*)(ah + off) = make_uint2(p0, p1);                           \
        }                                                                       \
    } while (0)

    // ===== stage 1: H[128,64] = X[128,2048] * A_e^T =====
    float acc1[4][4];
#pragma unroll
    for (int j = 0; j < 4; ++j)
#pragma unroll
        for (int q = 0; q < 4; ++q) acc1[j][q] = 0.f;

    // prologue: fill bufs 0,1; regs hold chunk 2
    LOAD_X(0);
    LOAD_A(0);
    STORE_X(0);
    STORE_A(0);
    LOAD_X(64);
    LOAD_A(64);
    STORE_X(1);
    STORE_A(1);
    LOAD_X(128);
    LOAD_A(128);
    __syncthreads();

    for (int c = 0; c < 32; ++c) {
        const uint32_t xbB = sbu + SM_X0 + (uint32_t)(c & 3) * X_STRIDE;
        const uint32_t ahB = sbu + SM_A0 + (uint32_t)(c & 3) * A_STRIDE;
#pragma unroll
        for (int kk = 0; kk < 4; ++kk) {
            // issue all three ldmatrix before any MMA (2+ loads in flight)
            uint32_t xf[4], bh[2][4];
            uint32_t xo = swz((uint32_t)(s1mg * 16) * 128 + apat + kk * 32);
            ldm_x4(xbB + xo, xf);
            uint32_t ao0 = swz((uint32_t)(s1ng * 32) * 128 + bpair + kk * 32);
            uint32_t ao1 = swz((uint32_t)(s1ng * 32 + 16) * 128 + bpair + kk * 32);
            ldm_x4(ahB + ao0, bh[0]);
            ldm_x4(ahB + ao1, bh[1]);
#pragma unroll
            for (int jj = 0; jj < 2; ++jj) {
                mma16816(acc1[jj * 2], xf, bh[jj]);
                mma16816(acc1[jj * 2 + 1], xf, bh[jj] + 2);
            }
        }
        if (c < 30) {
            STORE_X((c + 2) & 3);
            STORE_A((c + 2) & 3);
        }
        if (c < 29) {
            LOAD_X((c + 3) * 64);
            LOAD_A((c + 3) * 64);
        }
        if (c & 1) __syncthreads();
    }

    // ===== stage 2 fills (B): 128n x 64r fp32 per chunk =====
    // Rows PERMUTED within each 16-block: n16 -> (n16&1)*8 + (n16>>1) so the two
    // n8 MMA tiles interleave -> epilogue writes 4 contiguous n per thread.
    const int bfn = tid >> 3, bfq = tid & 7;
    float4 vb[4];

#define LOAD_B(N0)                                                              \
    do {                                                                        \
        const float* s0 = Brow + (size_t)((N0) + bfn) * RNK + bfq * 4;          \
        const float* s1 = Brow + (size_t)((N0) + bfn + 64) * RNK + bfq * 4;     \
        vb[0] = *(const float4*)(s0);                                           \
        vb[1] = *(const float4*)(s0 + 32);                                      \
        vb[2] = *(const float4*)(s1);                                           \
        vb[3] = *(const float4*)(s1 + 32);                                      \
    } while (0)

#define STORE_B(BUF)                                                            \
    do {                                                                        \
        char* bh_ = smc + SM_B0 + (BUF) * B_STRIDE;                             \
        _Pragma("unroll") for (int i = 0; i < 4; ++i) {                         \
            uint32_t p0 = pk2(vb[i].x, vb[i].y);                                \
            uint32_t p1 = pk2(vb[i].z, vb[i].w);                                \
            uint32_t r_ = (uint32_t)bfn + (i >> 1) * 64;                        \
            uint32_t n16_ = r_ & 15u;                                           \
            uint32_t rs_ = (r_ & ~15u) + ((n16_ & 1u) << 3) + (n16_ >> 1);      \
            uint32_t off = swz(rs_ * 128 + bfq * 8 + (i & 1) * 64);             \
            *(uint2*)(bh_ + off) = make_uint2(p0, p1);                          \
        }                                                                       \
    } while (0)

    LOAD_B(0);   // start GMEM reads early (X region safe: synced after c=31)

    // ===== H -> SMEM fp16 (fragment-consistent layout) =====
    {
        char* hh = smc + SM_H;
#pragma unroll
        for (int j = 0; j < 4; ++j) {
            int col = s1ng * 32 + j * 8 + 2 * tq;
            int r0 = s1mg * 16 + g;
            uint32_t p0 = pk2(acc1[j][0], acc1[j][1]);
            *(uint32_t*)(hh + swz((uint32_t)r0 * 128 + (uint32_t)col * 2)) = p0;
            uint32_t p1 = pk2(acc1[j][2], acc1[j][3]);
            *(uint32_t*)(hh + swz((uint32_t)(r0 + 8) * 128 + (uint32_t)col * 2)) = p1;
        }
    }
    STORE_B(0);
    LOAD_B(128);
    STORE_B(1);
    LOAD_B(256);
    __syncthreads();

    // preload ALL H fragments into registers (reused across all 16 n-chunks)
    uint32_t hf[2][4][4];
#pragma unroll
    for (int mt = 0; mt < 2; ++mt)
#pragma unroll
        for (int kk = 0; kk < 4; ++kk) {
            uint32_t ho = swz((uint32_t)(s2mg * 32 + mt * 16) * 128 + apat + kk * 32);
            ldm_x4(sbu + SM_H + ho, hf[mt][kk]);
        }

    // stage-2 output tokens for this warp
    int tko[2][2];
#pragma unroll
    for (int mt = 0; mt < 2; ++mt) {
        tko[mt][0] = tok[s2mg * 32 + mt * 16 + g];
        tko[mt][1] = tok[s2mg * 32 + mt * 16 + 8 + g];
    }

    // ===== stage 2: O[128,2048] = H[128,64] * B_e^T, 16 n-chunks of 128 =====
    for (int nc = 0; nc < 16; ++nc) {
        float acc2[2][4][4];
#pragma unroll
        for (int mt = 0; mt < 2; ++mt)
#pragma unroll
            for (int j = 0; j < 4; ++j)
#pragma unroll
                for (int q = 0; q < 4; ++q) acc2[mt][j][q] = 0.f;

        const uint32_t bbB = sbu + SM_B0 + (uint32_t)(nc & 3) * B_STRIDE;
#pragma unroll
        for (int kk = 0; kk < 4; ++kk) {
            uint32_t bh[2][4];
            uint32_t bo0 = swz((uint32_t)(s2ng * 32) * 128 + bpair + kk * 32);
            uint32_t bo1 = swz((uint32_t)(s2ng * 32 + 16) * 128 + bpair + kk * 32);
            ldm_x4(bbB + bo0, bh[0]);
            ldm_x4(bbB + bo1, bh[1]);
#pragma unroll
            for (int jj = 0; jj < 2; ++jj)
#pragma unroll
                for (int mt = 0; mt < 2; ++mt) {
                    mma16816(acc2[mt][jj * 2], hf[mt][kk], bh[jj]);
                    mma16816(acc2[mt][jj * 2 + 1], hf[mt][kk], bh[jj] + 2);
                }
        }

        // epilogue: STG.128 evict-first, 4 contiguous cols per thread
        const int nb0 = nc * 128 + s2ng * 32 + 4 * tq;
#pragma unroll
        for (int mt = 0; mt < 2; ++mt)
#pragma unroll
            for (int jj = 0; jj < 2; ++jj) {
                int colo = nb0 + jj * 16;
                float* t0 = acc2[mt][jj * 2];
                float* t1 = acc2[mt][jj * 2 + 1];
                if (tko[mt][0] >= 0)
                    __stcs((float4*)(out + (size_t)tko[mt][0] * DIM + colo),
                           make_float4(t0[0], t1[0], t0[1], t1[1]));
                if (tko[mt][1] >= 0)
                    __stcs((float4*)(out + (size_t)tko[mt][1] * DIM + colo),
                           make_float4(t0[2], t1[2], t0[3], t1[3]));
            }

        if (nc < 14) STORE_B((nc + 2) & 3);
        if (nc < 13) LOAD_B((nc + 3) * 128);
        if (nc & 1) __syncthreads();
    }
}

// ---------------- launch ----------------
extern "C" void kernel_launch(void* const* d_in, const int* in_sizes, int n_in,
                              void* d_out, int out_size) {
    const float* x  = (const float*)d_in[0];   // [B,S,D]
    const float* Aw = (const float*)d_in[1];   // [E,R,D]
    const float* Bw = (const float*)d_in[2];   // [E,D,R]
    const int*   ti = (const int*)d_in[3];     // [B,S]
    float* out = (float*)d_out;
    (void)in_sizes; (void)n_in; (void)out_size;

    static int smem_set = 0;
    if (!smem_set) {
        cudaFuncSetAttribute(k_main, cudaFuncAttributeMaxDynamicSharedMemorySize, SMEM_BYTES);
        smem_set = 1;
    }

    k_sort<<<E_N, 1024>>>(ti);
    dim3 grid(NTOK / TM, E_N, 1);
    k_main<<<grid, NTHR, SMEM_BYTES>>>(x, Aw, Bw, out);
}